// round 15
// baseline (speedup 1.0000x reference)
#include <cuda_runtime.h>
#include <cuda_fp16.h>
#include <math.h>
#include <stdint.h>

#define B_ 8
#define N_ 1024
#define E_ 768
#define H_ 12
#define D_ 64
#define M_ (B_*N_)   // 8192

// ---------------------------------------------------------------------------
// Scratch (__device__ globals; no allocations allowed)
// ---------------------------------------------------------------------------
__device__ __half g_x[(size_t)M_ * E_];
__device__ __half g_wq[(size_t)3*E_ * E_];
__device__ __half g_wp[(size_t)E_ * E_];
__device__ __half g_ao[(size_t)M_ * E_];
__device__ __half g_q2[(size_t)B_*H_*N_*D_];   // Q pre-scaled by 0.125*log2(e)
__device__ __half g_k2[(size_t)B_*H_*N_*D_];
__device__ __half g_vt[(size_t)B_*H_*D_*N_];
__device__ float2 g_rope[H_ * 32];

// ---------------------------------------------------------------------------
// PTX helpers
// ---------------------------------------------------------------------------
__device__ __forceinline__ uint32_t smem_u32(const void* p) {
    uint32_t a;
    asm("{ .reg .u64 t; cvta.to.shared.u64 t, %1; cvt.u32.u64 %0, t; }" : "=r"(a) : "l"(p));
    return a;
}
#define CPA16(dst, src) \
    asm volatile("cp.async.cg.shared.global [%0], [%1], 16;" :: "r"(dst), "l"(src) : "memory")
#define CP_COMMIT() asm volatile("cp.async.commit_group;" ::: "memory")
#define CP_WAIT1()  asm volatile("cp.async.wait_group 1;" ::: "memory")

__device__ __forceinline__ void ldsm_x4(uint32_t addr, uint32_t& r0, uint32_t& r1,
                                        uint32_t& r2, uint32_t& r3) {
    asm volatile("ldmatrix.sync.aligned.m8n8.x4.shared.b16 {%0,%1,%2,%3}, [%4];"
                 : "=r"(r0), "=r"(r1), "=r"(r2), "=r"(r3) : "r"(addr));
}
__device__ __forceinline__ void mma_f16(float* c, const uint32_t* a, const uint32_t* b) {
    asm volatile("mma.sync.aligned.m16n8k16.row.col.f32.f16.f16.f32 "
        "{%0,%1,%2,%3}, {%4,%5,%6,%7}, {%8,%9}, {%0,%1,%2,%3};"
        : "+f"(c[0]), "+f"(c[1]), "+f"(c[2]), "+f"(c[3])
        : "r"(a[0]), "r"(a[1]), "r"(a[2]), "r"(a[3]), "r"(b[0]), "r"(b[1]));
}
__device__ __forceinline__ uint32_t packh2(float a, float b) {
    __half2 t = __floats2half2_rn(a, b);
    return *(uint32_t*)&t;
}

// ---------------------------------------------------------------------------
// convert / init kernels
// ---------------------------------------------------------------------------
__global__ void convert_h(const float4* __restrict__ in, uint2* __restrict__ outp, int n4)
{
    int i = blockIdx.x * blockDim.x + threadIdx.x;
    if (i >= n4) return;
    float4 v = in[i];
    uint2 H;
    H.x = packh2(v.x, v.y);
    H.y = packh2(v.z, v.w);
    outp[i] = H;
}

__global__ void convert_w_t(const float* __restrict__ W,
                            __half* __restrict__ T, int K, int N)
{
    __shared__ float tile[32][33];
    int n0 = blockIdx.x * 32, k0 = blockIdx.y * 32;
    int tx = threadIdx.x, ty = threadIdx.y;
    for (int i = ty; i < 32; i += 8)
        tile[i][tx] = W[(size_t)(k0 + i) * N + n0 + tx];
    __syncthreads();
    for (int i = ty; i < 32; i += 8)
        T[(size_t)(n0 + i) * K + k0 + tx] = __float2half_rn(tile[tx][i]);
}

__global__ void rope_init(float2* __restrict__ tbl)
{
    int i = threadIdx.x + blockIdx.x * blockDim.x;
    if (i >= H_ * 32) return;
    int h = i >> 5, d2 = i & 31;
    float f = (float)h * exp2f(-(float)d2 * (13.287712379549449f / 32.0f));
    float s, c;
    sincosf(f, &s, &c);
    tbl[i] = make_float2(c, s);
}

// ---------------------------------------------------------------------------
// GEMM mainloop (R14-measured best): 4 warps, warp tile 64x64, BK=64, 2-stage.
// ---------------------------------------------------------------------------
__device__ __forceinline__ void gemm_mainloop(
    uint32_t sbase, int tid, int lane, int wm, int wn,
    const __half* __restrict__ Am, const __half* __restrict__ Bm,
    int m0, int n0, int Ktot, float (&acc)[4][8][4])
{
    const int NCH = Ktot / 64;

    auto load_stage = [&](int ch, int st) {
        uint32_t sb = sbase + (uint32_t)st * 32768u;
        int kb = ch * 64;
        #pragma unroll
        for (int u = 0; u < 8; u++) {
            int idx = tid + u * 128;
            int row = idx >> 3, chunk = idx & 7;
            uint32_t soff = (uint32_t)(row * 128 + ((chunk ^ (row & 7)) * 16));
            size_t ga = (size_t)(m0 + row) * Ktot + kb + chunk * 8;
            size_t gb = (size_t)(n0 + row) * Ktot + kb + chunk * 8;
            CPA16(sb +          soff, (const void*)(Am + ga));
            CPA16(sb + 16384u + soff, (const void*)(Bm + gb));
        }
    };

    auto compute_stage = [&](int st) {
        uint32_t sA = sbase + (uint32_t)st * 32768u;
        #pragma unroll
        for (int ks = 0; ks < 4; ks++) {
            int c2 = ks * 2 + (lane >> 4);
            uint32_t af[4][4];
            #pragma unroll
            for (int mi = 0; mi < 4; mi++) {
                int r = wm * 64 + mi * 16 + (lane & 15);
                uint32_t off = (uint32_t)(r * 128 + ((c2 ^ (r & 7)) * 16));
                ldsm_x4(sA + off, af[mi][0], af[mi][1], af[mi][2], af[mi][3]);
            }
            uint32_t bf[8][2];
            #pragma unroll
            for (int p = 0; p < 4; p++) {
                int r = wn * 64 + p * 16 + (lane & 15);
                uint32_t off = (uint32_t)(r * 128 + ((c2 ^ (r & 7)) * 16));
                uint32_t t0, t1, t2, t3;
                ldsm_x4(sA + 16384u + off, t0, t1, t2, t3);
                bf[2*p][0] = t0; bf[2*p][1] = t2; bf[2*p+1][0] = t1; bf[2*p+1][1] = t3;
            }
            #pragma unroll
            for (int mi = 0; mi < 4; mi++)
                #pragma unroll
                for (int ni = 0; ni < 8; ni++)
                    mma_f16(acc[mi][ni], af[mi], bf[ni]);
        }
    };

    load_stage(0, 0); CP_COMMIT();
    load_stage(1, 1); CP_COMMIT();

    for (int ch = 0; ch < NCH; ch++) {
        CP_WAIT1();
        __syncthreads();
        compute_stage(ch & 1);
        __syncthreads();
        if (ch + 2 < NCH) load_stage(ch + 2, ch & 1);
        CP_COMMIT();
    }
}

// ---------------------------------------------------------------------------
// Fused QKV GEMM: bias + RoPE (table); Q scaled by 0.125*log2e for exp2 softmax.
// ---------------------------------------------------------------------------
__global__ __launch_bounds__(128, 2)
void tc_gemm_qkv(const __half* __restrict__ Am, const __half* __restrict__ Bm,
                 const float* __restrict__ bias, const float2* __restrict__ rope,
                 __half* __restrict__ Qf, __half* __restrict__ Kf,
                 __half* __restrict__ Vt)
{
    extern __shared__ char smem[];
    uint32_t sbase = smem_u32(smem);
    int tid = threadIdx.x, lane = tid & 31, wid = tid >> 5;
    int wm = wid & 1, wn = wid >> 1;
    int m0 = blockIdx.y * 128, n0 = blockIdx.x * 128;

    float acc[4][8][4];
    #pragma unroll
    for (int mi = 0; mi < 4; mi++)
        #pragma unroll
        for (int ni = 0; ni < 8; ni++)
            #pragma unroll
            for (int e = 0; e < 4; e++) acc[mi][ni][e] = 0.f;

    gemm_mainloop(sbase, tid, lane, wm, wn, Am, Bm, m0, n0, E_, acc);
    __syncthreads();   // V branch reuses smem

    #pragma unroll
    for (int ni = 0; ni < 8; ni++) {
        int col = n0 + wn * 64 + ni * 8 + (lane & 3) * 2;
        float2 bv = *(const float2*)&bias[col];
        #pragma unroll
        for (int mi = 0; mi < 4; mi++) {
            acc[mi][ni][0] += bv.x; acc[mi][ni][1] += bv.y;
            acc[mi][ni][2] += bv.x; acc[mi][ni][3] += bv.y;
        }
    }

    int sec = n0 / 768;
    int nsec = n0 - sec * 768;
    int b = m0 >> 10;
    int t_base = m0 & 1023;

    if (sec < 2) {
        int h = nsec / 64 + wn;
        int bh = b * H_ + h;
        float cs[8], sn[8];
        #pragma unroll
        for (int u = 0; u < 8; u++) {
            int d2 = (u >> 1) * 8 + (lane & 3) * 2 + (u & 1);
            float2 r2 = rope[h * 32 + d2];
            cs[u] = r2.x; sn[u] = r2.y;
        }
        __half* Of = (sec == 0) ? Qf : Kf;
        // Q carries softmax scale AND log2(e) so attention can use exp2.
        const float scale = (sec == 0) ? 0.18033688011112042f : 1.0f;

        #pragma unroll
        for (int mi = 0; mi < 4; mi++) {
            int rbase = wm * 64 + mi * 16 + (lane >> 2);
            #pragma unroll
            for (int eh = 0; eh < 2; eh++) {
                int t = t_base + rbase + eh * 8;
                size_t rowoff = ((size_t)bh * N_ + t) * (size_t)D_;
                #pragma unroll
                for (int ni = 0; ni < 4; ni++) {
                    float a0 = acc[mi][ni][eh*2+0], b0 = acc[mi][ni+4][eh*2+0];
                    float a1 = acc[mi][ni][eh*2+1], b1 = acc[mi][ni+4][eh*2+1];
                    int u0 = ni * 2, u1 = u0 + 1;
                    float lo0 = (a0 * cs[u0] - b0 * sn[u0]) * scale;
                    float hi0 = (b0 * cs[u0] + a0 * sn[u0]) * scale;
                    float lo1 = (a1 * cs[u1] - b1 * sn[u1]) * scale;
                    float hi1 = (b1 * cs[u1] + a1 * sn[u1]) * scale;
                    int d0 = ni * 8 + (lane & 3) * 2;
                    *(uint32_t*)(Of + rowoff + d0)      = packh2(lo0, lo1);
                    *(uint32_t*)(Of + rowoff + d0 + 32) = packh2(hi0, hi1);
                }
            }
        }
    } else {
        float* sv = (float*)smem;
        #pragma unroll
        for (int mi = 0; mi < 4; mi++)
            #pragma unroll
            for (int ni = 0; ni < 8; ni++)
                #pragma unroll
                for (int e = 0; e < 4; e++) {
                    int col = wn * 64 + ni * 8 + (lane & 3) * 2 + (e & 1);
                    int r = wm * 64 + mi * 16 + (lane >> 2) + ((e >> 1) * 8);
                    sv[col * 129 + r] = acc[mi][ni][e];
                }
        __syncthreads();
        for (int i = tid; i < 128 * 32; i += 128) {
            int col = i >> 5, t4 = (i & 31) * 4;
            float v0 = sv[col * 129 + t4 + 0];
            float v1 = sv[col * 129 + t4 + 1];
            float v2 = sv[col * 129 + t4 + 2];
            float v3 = sv[col * 129 + t4 + 3];
            int hv = nsec / 64 + (col >> 6);
            int d = col & 63;
            int bhv = b * H_ + hv;
            size_t ob = ((size_t)bhv * D_ + d) * (size_t)N_ + t_base + t4;
            uint2 Hv;
            Hv.x = packh2(v0, v1);
            Hv.y = packh2(v2, v3);
            *(uint2*)(Vt + ob) = Hv;
        }
    }
}

// ---------------------------------------------------------------------------
// Plain GEMM (projection)
// ---------------------------------------------------------------------------
__global__ __launch_bounds__(128, 2)
void tc_gemm(const __half* __restrict__ Am, const __half* __restrict__ Bm,
             const float* __restrict__ bias, float* __restrict__ C,
             int Ntot, int Ktot)
{
    extern __shared__ char smem[];
    uint32_t sbase = smem_u32(smem);
    int tid = threadIdx.x, lane = tid & 31, wid = tid >> 5;
    int wm = wid & 1, wn = wid >> 1;
    int m0 = blockIdx.y * 128, n0 = blockIdx.x * 128;

    float acc[4][8][4];
    #pragma unroll
    for (int mi = 0; mi < 4; mi++)
        #pragma unroll
        for (int ni = 0; ni < 8; ni++)
            #pragma unroll
            for (int e = 0; e < 4; e++) acc[mi][ni][e] = 0.f;

    gemm_mainloop(sbase, tid, lane, wm, wn, Am, Bm, m0, n0, Ktot, acc);

    #pragma unroll
    for (int mi = 0; mi < 4; mi++) {
        #pragma unroll
        for (int ni = 0; ni < 8; ni++) {
            int row = m0 + wm * 64 + mi * 16 + (lane >> 2);
            int col = n0 + wn * 64 + ni * 8 + (lane & 3) * 2;
            float2 bv = *(const float2*)&bias[col];
            float2 v0 = {acc[mi][ni][0] + bv.x, acc[mi][ni][1] + bv.y};
            float2 v1 = {acc[mi][ni][2] + bv.x, acc[mi][ni][3] + bv.y};
            *(float2*)&C[(size_t)row * Ntot + col] = v0;
            *(float2*)&C[(size_t)(row + 8) * Ntot + col] = v1;
        }
    }
}

// ---------------------------------------------------------------------------
// Flash attention (fp16, exp2/h2exp2 softmax, 128-key stages):
// 8 warps x 16 q rows, 128 q/CTA. Stage = 32KB: K sub0 @+0, K sub1 @+8K,
// V sub0 @+16K, V sub1 @+24K (each 64x128B, XOR-8 swizzle).
// Smem: Q@0 (16K) + 2 stages x 32K = 80KB. 8 outer iters, 1 sync pair each.
// ---------------------------------------------------------------------------
__global__ __launch_bounds__(256, 2) void attn_mma(
    const __half* __restrict__ Qf, const __half* __restrict__ Kf,
    const __half* __restrict__ Vt, __half* __restrict__ Oo)
{
    extern __shared__ char smem[];
    uint32_t sb = smem_u32(smem);
    const uint32_t oQ = 0, oStage = 16384;

    int tid = threadIdx.x, lane = tid & 31, wq = tid >> 5;
    int bh = blockIdx.y;
    int q0 = blockIdx.x * 128;
    int b = bh / H_, h = bh % H_;

    const __half* Qb = Qf + ((size_t)bh * N_ + q0) * D_;
    const __half* Kb = Kf + (size_t)bh * N_ * D_;
    const __half* Vb = Vt + (size_t)bh * D_ * N_;

    for (int u = tid; u < 1024; u += 256) {
        int r = u >> 3, chunk = u & 7;
        uint32_t off = (uint32_t)(r * 128 + ((chunk ^ (r & 7)) * 16));
        CPA16(sb + oQ + off, (const void*)(Qb + (size_t)r * D_ + chunk * 8));
    }

    // stage covers 128 keys: parts {K0, K1, V0, V1} x 8KB
    auto load_stage = [&](int it, int st) {
        int jt = it * 128;
        uint32_t s0 = sb + oStage + (uint32_t)st * 32768u;
        for (int u = tid; u < 2048; u += 256) {
            int part = u >> 9;
            int idx = u & 511;
            int r = idx >> 3, chunk = idx & 7;
            uint32_t off = (uint32_t)(r * 128 + ((chunk ^ (r & 7)) * 16));
            const __half* src;
            if (part == 0)      src = Kb + (size_t)(jt + r) * D_ + chunk * 8;
            else if (part == 1) src = Kb + (size_t)(jt + 64 + r) * D_ + chunk * 8;
            else if (part == 2) src = Vb + (size_t)r * N_ + jt + chunk * 8;
            else                src = Vb + (size_t)r * N_ + jt + 64 + chunk * 8;
            CPA16(s0 + (uint32_t)part * 8192u + off, (const void*)src);
        }
    };

    float o[8][4];
    #pragma unroll
    for (int i = 0; i < 8; i++)
        #pragma unroll
        for (int j = 0; j < 4; j++) o[i][j] = 0.f;
    float m0v = -1e30f, m1v = -1e30f, l0 = 0.f, l1 = 0.f;

    load_stage(0, 0); CP_COMMIT();
    load_stage(1, 1); CP_COMMIT();

    for (int it = 0; it < 8; it++) {
        CP_WAIT1();
        __syncthreads();
        uint32_t sStage = sb + oStage + (uint32_t)(it & 1) * 32768u;

        #pragma unroll
        for (int sub = 0; sub < 2; sub++) {
            uint32_t sK = sStage + (uint32_t)sub * 8192u;
            uint32_t sV = sStage + 16384u + (uint32_t)sub * 8192u;

            float c[8][4];
            #pragma unroll
            for (int i = 0; i < 8; i++)
                #pragma unroll
                for (int j = 0; j < 4; j++) c[i][j] = 0.f;

            // ---- S(log2) = Qs K^T ----
            #pragma unroll
            for (int ks = 0; ks < 4; ks++) {
                int chunk = ks * 2 + (lane >> 4);
                int rq = wq * 16 + (lane & 15);
                uint32_t offq = (uint32_t)(rq * 128 + ((chunk ^ (rq & 7)) * 16));
                uint32_t af[4];
                ldsm_x4(sb + oQ + offq, af[0], af[1], af[2], af[3]);
                uint32_t bf[8][2];
                #pragma unroll
                for (int p = 0; p < 4; p++) {
                    int rk = p * 16 + (lane & 15);
                    uint32_t offk = (uint32_t)(rk * 128 + ((chunk ^ (rk & 7)) * 16));
                    uint32_t t0, t1, t2, t3;
                    ldsm_x4(sK + offk, t0, t1, t2, t3);
                    bf[2*p][0] = t0; bf[2*p][1] = t2; bf[2*p+1][0] = t1; bf[2*p+1][1] = t3;
                }
                #pragma unroll
                for (int nt = 0; nt < 8; nt++) mma_f16(c[nt], af, bf[nt]);
            }

            // ---- online softmax in log2 domain; P via h2exp2 -> fp16 frags ----
            uint32_t ap[4][4];
            {
                float mt0 = -1e30f, mt1 = -1e30f;
                #pragma unroll
                for (int t = 0; t < 8; t++) {
                    mt0 = fmaxf(mt0, fmaxf(c[t][0], c[t][1]));
                    mt1 = fmaxf(mt1, fmaxf(c[t][2], c[t][3]));
                }
                mt0 = fmaxf(mt0, __shfl_xor_sync(0xffffffffu, mt0, 1));
                mt0 = fmaxf(mt0, __shfl_xor_sync(0xffffffffu, mt0, 2));
                mt1 = fmaxf(mt1, __shfl_xor_sync(0xffffffffu, mt1, 1));
                mt1 = fmaxf(mt1, __shfl_xor_sync(0xffffffffu, mt1, 2));
                float mn0 = fmaxf(m0v, mt0), mn1 = fmaxf(m1v, mt1);
                float f0 = exp2f(m0v - mn0), f1 = exp2f(m1v - mn1);
                m0v = mn0; m1v = mn1;
                float ps0 = 0.f, ps1 = 0.f;
                #pragma unroll
                for (int s = 0; s < 4; s++) {
                    #pragma unroll
                    for (int half = 0; half < 2; half++) {
                        int t = 2 * s + half;
                        __half2 e0 = h2exp2(__floats2half2_rn(c[t][0] - mn0, c[t][1] - mn0));
                        __half2 e1 = h2exp2(__floats2half2_rn(c[t][2] - mn1, c[t][3] - mn1));
                        ap[s][half * 2 + 0] = *(uint32_t*)&e0;
                        ap[s][half * 2 + 1] = *(uint32_t*)&e1;
                        float2 fa = __half22float2(e0);
                        float2 fb = __half22float2(e1);
                        ps0 += fa.x + fa.y;
                        ps1 += fb.x + fb.y;
                    }
                }
                ps0 += __shfl_xor_sync(0xffffffffu, ps0, 1);
                ps0 += __shfl_xor_sync(0xffffffffu, ps0, 2);
                ps1 += __shfl_xor_sync(0xffffffffu, ps1, 1);
                ps1 += __shfl_xor_sync(0xffffffffu, ps1, 2);
                l0 = l0 * f0 + ps0;
                l1 = l1 * f1 + ps1;
                #pragma unroll
                for (int t = 0; t < 8; t++) {
                    o[t][0] *= f0; o[t][1] *= f0;
                    o[t][2] *= f1; o[t][3] *= f1;
                }
            }

            // ---- O += P V ----
            #pragma unroll
            for (int s = 0; s < 4; s++) {
                int chunk = s * 2 + (lane >> 4);
                uint32_t bf[8][2];
                #pragma unroll
                for (int p = 0; p < 4; p++) {
                    int rd = p * 16 + (lane & 15);
                    uint32_t off = (uint32_t)(rd * 128 + ((chunk ^ (rd & 7)) * 16));
                    uint32_t t0, t1, t2, t3;
                    ldsm_x4(sV + off, t0, t1, t2, t3);
                    bf[2*p][0] = t0; bf[2*p][1] = t2; bf[2*p+1][0] = t1; bf[2*p+1][1] = t3;
                }
                #pragma unroll
                for (int nt = 0; nt < 8; nt++) mma_f16(o[nt], ap[s], bf[nt]);
            }
        }

        __syncthreads();
        if (it + 2 < 8) load_stage(it + 2, it & 1);
        CP_COMMIT();
    }

    float inv0 = 1.0f / l0, inv1 = 1.0f / l1;
    int r = lane >> 2;
    int row0 = q0 + wq * 16 + r;
    size_t base0 = ((size_t)(b * N_) + row0) * E_ + h * 64 + (lane & 3) * 2;
    size_t base1 = base0 + (size_t)8 * E_;
    #pragma unroll
    for (int t = 0; t < 8; t++) {
        *(uint32_t*)(Oo + base0 + t * 8) = packh2(o[t][0] * inv0, o[t][1] * inv0);
        *(uint32_t*)(Oo + base1 + t * 8) = packh2(o[t][2] * inv1, o[t][3] * inv1);
    }
}

// ---------------------------------------------------------------------------
extern "C" void kernel_launch(void* const* d_in, const int* in_sizes, int n_in,
                              void* d_out, int out_size)
{
    (void)in_sizes; (void)n_in; (void)out_size;
    const float* x      = (const float*)d_in[0];
    const float* w_qkv  = (const float*)d_in[1];
    const float* b_qkv  = (const float*)d_in[2];
    const float* w_proj = (const float*)d_in[3];
    const float* b_proj = (const float*)d_in[4];
    float* out = (float*)d_out;

    __half *xf, *wq, *wp, *ao, *q2, *k2, *vt;
    float2* rope;
    cudaGetSymbolAddress((void**)&xf, g_x);
    cudaGetSymbolAddress((void**)&wq, g_wq);
    cudaGetSymbolAddress((void**)&wp, g_wp);
    cudaGetSymbolAddress((void**)&ao, g_ao);
    cudaGetSymbolAddress((void**)&q2, g_q2);
    cudaGetSymbolAddress((void**)&k2, g_k2);
    cudaGetSymbolAddress((void**)&vt, g_vt);
    cudaGetSymbolAddress((void**)&rope, g_rope);

    const int GEMM_SMEM = 66560;
    cudaFuncSetAttribute(tc_gemm_qkv, cudaFuncAttributeMaxDynamicSharedMemorySize, GEMM_SMEM);
    cudaFuncSetAttribute(tc_gemm, cudaFuncAttributeMaxDynamicSharedMemorySize, GEMM_SMEM);
    const int ATTN_SMEM = 16384 + 2 * 32768;   // Q 16K + 2 stages x 32K = 80KB
    cudaFuncSetAttribute(attn_mma, cudaFuncAttributeMaxDynamicSharedMemorySize, ATTN_SMEM);

    rope_init<<<2, 192>>>(rope);
    {
        int n4 = M_ * E_ / 4;
        convert_h<<<(n4 + 255) / 256, 256>>>((const float4*)x, (uint2*)xf, n4);
    }
    {
        dim3 blk(32, 8);
        convert_w_t<<<dim3(3 * E_ / 32, E_ / 32), blk>>>(w_qkv, wq, E_, 3 * E_);
        convert_w_t<<<dim3(E_ / 32, E_ / 32), blk>>>(w_proj, wp, E_, E_);
    }
    {
        dim3 grid(3 * E_ / 128, M_ / 128);
        tc_gemm_qkv<<<grid, 128, GEMM_SMEM>>>(xf, wq, b_qkv, rope, q2, k2, vt);
    }
    {
        dim3 grid(N_ / 128, B_ * H_);
        attn_mma<<<grid, 256, ATTN_SMEM>>>(q2, k2, vt, ao);
    }
    {
        dim3 grid(E_ / 128, M_ / 128);
        tc_gemm<<<grid, 128, GEMM_SMEM>>>(ao, wp, b_proj, out, E_, E_);
    }
}

// round 16
// speedup vs baseline: 1.0251x; 1.0251x over previous
#include <cuda_runtime.h>
#include <cuda_fp16.h>
#include <math.h>
#include <stdint.h>

#define B_ 8
#define N_ 1024
#define E_ 768
#define H_ 12
#define D_ 64
#define M_ (B_*N_)   // 8192

// ---------------------------------------------------------------------------
// Scratch (__device__ globals; no allocations allowed)
// ---------------------------------------------------------------------------
__device__ __half g_x[(size_t)M_ * E_];
__device__ __half g_wq[(size_t)3*E_ * E_];
__device__ __half g_wp[(size_t)E_ * E_];
__device__ __half g_ao[(size_t)M_ * E_];
__device__ __half g_q2[(size_t)B_*H_*N_*D_];   // Q pre-scaled by 0.125*log2(e)
__device__ __half g_k2[(size_t)B_*H_*N_*D_];
__device__ __half g_vt[(size_t)B_*H_*D_*N_];
__device__ float2 g_rope[H_ * 32];

// ---------------------------------------------------------------------------
// PTX helpers
// ---------------------------------------------------------------------------
__device__ __forceinline__ uint32_t smem_u32(const void* p) {
    uint32_t a;
    asm("{ .reg .u64 t; cvta.to.shared.u64 t, %1; cvt.u32.u64 %0, t; }" : "=r"(a) : "l"(p));
    return a;
}
#define CPA16(dst, src) \
    asm volatile("cp.async.cg.shared.global [%0], [%1], 16;" :: "r"(dst), "l"(src) : "memory")
#define CP_COMMIT() asm volatile("cp.async.commit_group;" ::: "memory")
#define CP_WAIT1()  asm volatile("cp.async.wait_group 1;" ::: "memory")

__device__ __forceinline__ void ldsm_x4(uint32_t addr, uint32_t& r0, uint32_t& r1,
                                        uint32_t& r2, uint32_t& r3) {
    asm volatile("ldmatrix.sync.aligned.m8n8.x4.shared.b16 {%0,%1,%2,%3}, [%4];"
                 : "=r"(r0), "=r"(r1), "=r"(r2), "=r"(r3) : "r"(addr));
}
__device__ __forceinline__ void mma_f16(float* c, const uint32_t* a, const uint32_t* b) {
    asm volatile("mma.sync.aligned.m16n8k16.row.col.f32.f16.f16.f32 "
        "{%0,%1,%2,%3}, {%4,%5,%6,%7}, {%8,%9}, {%0,%1,%2,%3};"
        : "+f"(c[0]), "+f"(c[1]), "+f"(c[2]), "+f"(c[3])
        : "r"(a[0]), "r"(a[1]), "r"(a[2]), "r"(a[3]), "r"(b[0]), "r"(b[1]));
}
__device__ __forceinline__ uint32_t packh2(float a, float b) {
    __half2 t = __floats2half2_rn(a, b);
    return *(uint32_t*)&t;
}

// ---------------------------------------------------------------------------
// Fused prep: x convert | wq transpose | wp transpose | rope table.
// Grid partitioned by blockIdx.x. 256 threads.
// ---------------------------------------------------------------------------
#define XBLOCKS 6144                    // M*E/4 / 256
#define WQTILES 1728                    // (2304/32)*(768/32)
#define WPTILES 576                     // (768/32)*(768/32)
__global__ void prep_all(const float4* __restrict__ x4, uint2* __restrict__ xf,
                         const float* __restrict__ Wq, __half* __restrict__ Tq,
                         const float* __restrict__ Wp, __half* __restrict__ Tp,
                         float2* __restrict__ rope)
{
    __shared__ float tile[32][33];
    int blk = blockIdx.x;
    int tid = threadIdx.x;

    if (blk < XBLOCKS) {
        int i = blk * 256 + tid;
        float4 v = x4[i];
        uint2 Hv;
        Hv.x = packh2(v.x, v.y);
        Hv.y = packh2(v.z, v.w);
        xf[i] = Hv;
    } else if (blk < XBLOCKS + WQTILES + WPTILES) {
        const float* W;
        __half* T;
        int t, Nn;
        if (blk < XBLOCKS + WQTILES) {
            t = blk - XBLOCKS; W = Wq; T = Tq; Nn = 3 * E_;
        } else {
            t = blk - XBLOCKS - WQTILES; W = Wp; T = Tp; Nn = E_;
        }
        int ntiles = Nn / 32;
        int n0 = (t % ntiles) * 32, k0 = (t / ntiles) * 32;
        int tx = tid & 31, ty = tid >> 5;
        for (int i = ty; i < 32; i += 8)
            tile[i][tx] = W[(size_t)(k0 + i) * Nn + n0 + tx];
        __syncthreads();
        for (int i = ty; i < 32; i += 8)
            T[(size_t)(n0 + i) * E_ + k0 + tx] = __float2half_rn(tile[tx][i]);
    } else {
        int i = (blk - XBLOCKS - WQTILES - WPTILES) * 256 + tid;
        if (i < H_ * 32) {
            int h = i >> 5, d2 = i & 31;
            float f = (float)h * exp2f(-(float)d2 * (13.287712379549449f / 32.0f));
            float s, c;
            sincosf(f, &s, &c);
            rope[i] = make_float2(c, s);
        }
    }
}

// ---------------------------------------------------------------------------
// GEMM mainloop (R14-measured best): 4 warps, warp tile 64x64, BK=64, 2-stage.
// ---------------------------------------------------------------------------
__device__ __forceinline__ void gemm_mainloop(
    uint32_t sbase, int tid, int lane, int wm, int wn,
    const __half* __restrict__ Am, const __half* __restrict__ Bm,
    int m0, int n0, int Ktot, float (&acc)[4][8][4])
{
    const int NCH = Ktot / 64;

    auto load_stage = [&](int ch, int st) {
        uint32_t sb = sbase + (uint32_t)st * 32768u;
        int kb = ch * 64;
        #pragma unroll
        for (int u = 0; u < 8; u++) {
            int idx = tid + u * 128;
            int row = idx >> 3, chunk = idx & 7;
            uint32_t soff = (uint32_t)(row * 128 + ((chunk ^ (row & 7)) * 16));
            size_t ga = (size_t)(m0 + row) * Ktot + kb + chunk * 8;
            size_t gb = (size_t)(n0 + row) * Ktot + kb + chunk * 8;
            CPA16(sb +          soff, (const void*)(Am + ga));
            CPA16(sb + 16384u + soff, (const void*)(Bm + gb));
        }
    };

    auto compute_stage = [&](int st) {
        uint32_t sA = sbase + (uint32_t)st * 32768u;
        #pragma unroll
        for (int ks = 0; ks < 4; ks++) {
            int c2 = ks * 2 + (lane >> 4);
            uint32_t af[4][4];
            #pragma unroll
            for (int mi = 0; mi < 4; mi++) {
                int r = wm * 64 + mi * 16 + (lane & 15);
                uint32_t off = (uint32_t)(r * 128 + ((c2 ^ (r & 7)) * 16));
                ldsm_x4(sA + off, af[mi][0], af[mi][1], af[mi][2], af[mi][3]);
            }
            uint32_t bf[8][2];
            #pragma unroll
            for (int p = 0; p < 4; p++) {
                int r = wn * 64 + p * 16 + (lane & 15);
                uint32_t off = (uint32_t)(r * 128 + ((c2 ^ (r & 7)) * 16));
                uint32_t t0, t1, t2, t3;
                ldsm_x4(sA + 16384u + off, t0, t1, t2, t3);
                bf[2*p][0] = t0; bf[2*p][1] = t2; bf[2*p+1][0] = t1; bf[2*p+1][1] = t3;
            }
            #pragma unroll
            for (int mi = 0; mi < 4; mi++)
                #pragma unroll
                for (int ni = 0; ni < 8; ni++)
                    mma_f16(acc[mi][ni], af[mi], bf[ni]);
        }
    };

    load_stage(0, 0); CP_COMMIT();
    load_stage(1, 1); CP_COMMIT();

    for (int ch = 0; ch < NCH; ch++) {
        CP_WAIT1();
        __syncthreads();
        compute_stage(ch & 1);
        __syncthreads();
        if (ch + 2 < NCH) load_stage(ch + 2, ch & 1);
        CP_COMMIT();
    }
}

// ---------------------------------------------------------------------------
// Fused QKV GEMM: bias + RoPE (table); Q scaled by 0.125*log2e for exp2 softmax.
// ---------------------------------------------------------------------------
__global__ __launch_bounds__(128, 2)
void tc_gemm_qkv(const __half* __restrict__ Am, const __half* __restrict__ Bm,
                 const float* __restrict__ bias, const float2* __restrict__ rope,
                 __half* __restrict__ Qf, __half* __restrict__ Kf,
                 __half* __restrict__ Vt)
{
    extern __shared__ char smem[];
    uint32_t sbase = smem_u32(smem);
    int tid = threadIdx.x, lane = tid & 31, wid = tid >> 5;
    int wm = wid & 1, wn = wid >> 1;
    int m0 = blockIdx.y * 128, n0 = blockIdx.x * 128;

    float acc[4][8][4];
    #pragma unroll
    for (int mi = 0; mi < 4; mi++)
        #pragma unroll
        for (int ni = 0; ni < 8; ni++)
            #pragma unroll
            for (int e = 0; e < 4; e++) acc[mi][ni][e] = 0.f;

    gemm_mainloop(sbase, tid, lane, wm, wn, Am, Bm, m0, n0, E_, acc);
    __syncthreads();   // V branch reuses smem

    #pragma unroll
    for (int ni = 0; ni < 8; ni++) {
        int col = n0 + wn * 64 + ni * 8 + (lane & 3) * 2;
        float2 bv = *(const float2*)&bias[col];
        #pragma unroll
        for (int mi = 0; mi < 4; mi++) {
            acc[mi][ni][0] += bv.x; acc[mi][ni][1] += bv.y;
            acc[mi][ni][2] += bv.x; acc[mi][ni][3] += bv.y;
        }
    }

    int sec = n0 / 768;
    int nsec = n0 - sec * 768;
    int b = m0 >> 10;
    int t_base = m0 & 1023;

    if (sec < 2) {
        int h = nsec / 64 + wn;
        int bh = b * H_ + h;
        float cs[8], sn[8];
        #pragma unroll
        for (int u = 0; u < 8; u++) {
            int d2 = (u >> 1) * 8 + (lane & 3) * 2 + (u & 1);
            float2 r2 = rope[h * 32 + d2];
            cs[u] = r2.x; sn[u] = r2.y;
        }
        __half* Of = (sec == 0) ? Qf : Kf;
        const float scale = (sec == 0) ? 0.18033688011112042f : 1.0f;

        #pragma unroll
        for (int mi = 0; mi < 4; mi++) {
            int rbase = wm * 64 + mi * 16 + (lane >> 2);
            #pragma unroll
            for (int eh = 0; eh < 2; eh++) {
                int t = t_base + rbase + eh * 8;
                size_t rowoff = ((size_t)bh * N_ + t) * (size_t)D_;
                #pragma unroll
                for (int ni = 0; ni < 4; ni++) {
                    float a0 = acc[mi][ni][eh*2+0], b0 = acc[mi][ni+4][eh*2+0];
                    float a1 = acc[mi][ni][eh*2+1], b1 = acc[mi][ni+4][eh*2+1];
                    int u0 = ni * 2, u1 = u0 + 1;
                    float lo0 = (a0 * cs[u0] - b0 * sn[u0]) * scale;
                    float hi0 = (b0 * cs[u0] + a0 * sn[u0]) * scale;
                    float lo1 = (a1 * cs[u1] - b1 * sn[u1]) * scale;
                    float hi1 = (b1 * cs[u1] + a1 * sn[u1]) * scale;
                    int d0 = ni * 8 + (lane & 3) * 2;
                    *(uint32_t*)(Of + rowoff + d0)      = packh2(lo0, lo1);
                    *(uint32_t*)(Of + rowoff + d0 + 32) = packh2(hi0, hi1);
                }
            }
        }
    } else {
        float* sv = (float*)smem;
        #pragma unroll
        for (int mi = 0; mi < 4; mi++)
            #pragma unroll
            for (int ni = 0; ni < 8; ni++)
                #pragma unroll
                for (int e = 0; e < 4; e++) {
                    int col = wn * 64 + ni * 8 + (lane & 3) * 2 + (e & 1);
                    int r = wm * 64 + mi * 16 + (lane >> 2) + ((e >> 1) * 8);
                    sv[col * 129 + r] = acc[mi][ni][e];
                }
        __syncthreads();
        for (int i = tid; i < 128 * 32; i += 128) {
            int col = i >> 5, t4 = (i & 31) * 4;
            float v0 = sv[col * 129 + t4 + 0];
            float v1 = sv[col * 129 + t4 + 1];
            float v2 = sv[col * 129 + t4 + 2];
            float v3 = sv[col * 129 + t4 + 3];
            int hv = nsec / 64 + (col >> 6);
            int d = col & 63;
            int bhv = b * H_ + hv;
            size_t ob = ((size_t)bhv * D_ + d) * (size_t)N_ + t_base + t4;
            uint2 Hv;
            Hv.x = packh2(v0, v1);
            Hv.y = packh2(v2, v3);
            *(uint2*)(Vt + ob) = Hv;
        }
    }
}

// ---------------------------------------------------------------------------
// Plain GEMM (projection)
// ---------------------------------------------------------------------------
__global__ __launch_bounds__(128, 2)
void tc_gemm(const __half* __restrict__ Am, const __half* __restrict__ Bm,
             const float* __restrict__ bias, float* __restrict__ C,
             int Ntot, int Ktot)
{
    extern __shared__ char smem[];
    uint32_t sbase = smem_u32(smem);
    int tid = threadIdx.x, lane = tid & 31, wid = tid >> 5;
    int wm = wid & 1, wn = wid >> 1;
    int m0 = blockIdx.y * 128, n0 = blockIdx.x * 128;

    float acc[4][8][4];
    #pragma unroll
    for (int mi = 0; mi < 4; mi++)
        #pragma unroll
        for (int ni = 0; ni < 8; ni++)
            #pragma unroll
            for (int e = 0; e < 4; e++) acc[mi][ni][e] = 0.f;

    gemm_mainloop(sbase, tid, lane, wm, wn, Am, Bm, m0, n0, Ktot, acc);

    #pragma unroll
    for (int mi = 0; mi < 4; mi++) {
        #pragma unroll
        for (int ni = 0; ni < 8; ni++) {
            int row = m0 + wm * 64 + mi * 16 + (lane >> 2);
            int col = n0 + wn * 64 + ni * 8 + (lane & 3) * 2;
            float2 bv = *(const float2*)&bias[col];
            float2 v0 = {acc[mi][ni][0] + bv.x, acc[mi][ni][1] + bv.y};
            float2 v1 = {acc[mi][ni][2] + bv.x, acc[mi][ni][3] + bv.y};
            *(float2*)&C[(size_t)row * Ntot + col] = v0;
            *(float2*)&C[(size_t)(row + 8) * Ntot + col] = v1;
        }
    }
}

// ---------------------------------------------------------------------------
// Flash attention (fp16, exp2 softmax, 128-key stages, Q frags in registers).
// 8 warps x 16 q rows. Stage 32KB: K0@+0, K1@+8K, V0@+16K, V1@+24K.
// Smem: Q@0 (16K) + 2 stages x 32K = 80KB, occ 2.
// ---------------------------------------------------------------------------
__global__ __launch_bounds__(256, 2) void attn_mma(
    const __half* __restrict__ Qf, const __half* __restrict__ Kf,
    const __half* __restrict__ Vt, __half* __restrict__ Oo)
{
    extern __shared__ char smem[];
    uint32_t sb = smem_u32(smem);
    const uint32_t oQ = 0, oStage = 16384;

    int tid = threadIdx.x, lane = tid & 31, wq = tid >> 5;
    int bh = blockIdx.y;
    int q0 = blockIdx.x * 128;
    int b = bh / H_, h = bh % H_;

    const __half* Qb = Qf + ((size_t)bh * N_ + q0) * D_;
    const __half* Kb = Kf + (size_t)bh * N_ * D_;
    const __half* Vb = Vt + (size_t)bh * D_ * N_;

    for (int u = tid; u < 1024; u += 256) {
        int r = u >> 3, chunk = u & 7;
        uint32_t off = (uint32_t)(r * 128 + ((chunk ^ (r & 7)) * 16));
        CPA16(sb + oQ + off, (const void*)(Qb + (size_t)r * D_ + chunk * 8));
    }

    auto load_stage = [&](int it, int st) {
        int jt = it * 128;
        uint32_t s0 = sb + oStage + (uint32_t)st * 32768u;
        for (int u = tid; u < 2048; u += 256) {
            int part = u >> 9;
            int idx = u & 511;
            int r = idx >> 3, chunk = idx & 7;
            uint32_t off = (uint32_t)(r * 128 + ((chunk ^ (r & 7)) * 16));
            const __half* src;
            if (part == 0)      src = Kb + (size_t)(jt + r) * D_ + chunk * 8;
            else if (part == 1) src = Kb + (size_t)(jt + 64 + r) * D_ + chunk * 8;
            else if (part == 2) src = Vb + (size_t)r * N_ + jt + chunk * 8;
            else                src = Vb + (size_t)r * N_ + jt + 64 + chunk * 8;
            CPA16(s0 + (uint32_t)part * 8192u + off, (const void*)src);
        }
    };

    float o[8][4];
    #pragma unroll
    for (int i = 0; i < 8; i++)
        #pragma unroll
        for (int j = 0; j < 4; j++) o[i][j] = 0.f;
    float m0v = -1e30f, m1v = -1e30f, l0 = 0.f, l1 = 0.f;

    uint32_t qfr[4][4];   // Q fragments, loaded once at it==0

    load_stage(0, 0); CP_COMMIT();
    load_stage(1, 1); CP_COMMIT();

    for (int it = 0; it < 8; it++) {
        CP_WAIT1();
        __syncthreads();
        uint32_t sStage = sb + oStage + (uint32_t)(it & 1) * 32768u;

        if (it == 0) {
            #pragma unroll
            for (int ks = 0; ks < 4; ks++) {
                int chunk = ks * 2 + (lane >> 4);
                int rq = wq * 16 + (lane & 15);
                uint32_t offq = (uint32_t)(rq * 128 + ((chunk ^ (rq & 7)) * 16));
                ldsm_x4(sb + oQ + offq, qfr[ks][0], qfr[ks][1], qfr[ks][2], qfr[ks][3]);
            }
        }

        #pragma unroll
        for (int sub = 0; sub < 2; sub++) {
            uint32_t sK = sStage + (uint32_t)sub * 8192u;
            uint32_t sV = sStage + 16384u + (uint32_t)sub * 8192u;

            float c[8][4];
            #pragma unroll
            for (int i = 0; i < 8; i++)
                #pragma unroll
                for (int j = 0; j < 4; j++) c[i][j] = 0.f;

            // ---- S(log2) = Qs K^T ----
            #pragma unroll
            for (int ks = 0; ks < 4; ks++) {
                int chunk = ks * 2 + (lane >> 4);
                uint32_t bf[8][2];
                #pragma unroll
                for (int p = 0; p < 4; p++) {
                    int rk = p * 16 + (lane & 15);
                    uint32_t offk = (uint32_t)(rk * 128 + ((chunk ^ (rk & 7)) * 16));
                    uint32_t t0, t1, t2, t3;
                    ldsm_x4(sK + offk, t0, t1, t2, t3);
                    bf[2*p][0] = t0; bf[2*p][1] = t2; bf[2*p+1][0] = t1; bf[2*p+1][1] = t3;
                }
                #pragma unroll
                for (int nt = 0; nt < 8; nt++) mma_f16(c[nt], qfr[ks], bf[nt]);
            }

            // ---- online softmax (log2 domain, h2exp2 -> P fp16 frags) ----
            uint32_t ap[4][4];
            {
                float mt0 = -1e30f, mt1 = -1e30f;
                #pragma unroll
                for (int t = 0; t < 8; t++) {
                    mt0 = fmaxf(mt0, fmaxf(c[t][0], c[t][1]));
                    mt1 = fmaxf(mt1, fmaxf(c[t][2], c[t][3]));
                }
                mt0 = fmaxf(mt0, __shfl_xor_sync(0xffffffffu, mt0, 1));
                mt0 = fmaxf(mt0, __shfl_xor_sync(0xffffffffu, mt0, 2));
                mt1 = fmaxf(mt1, __shfl_xor_sync(0xffffffffu, mt1, 1));
                mt1 = fmaxf(mt1, __shfl_xor_sync(0xffffffffu, mt1, 2));
                float mn0 = fmaxf(m0v, mt0), mn1 = fmaxf(m1v, mt1);
                float f0 = exp2f(m0v - mn0), f1 = exp2f(m1v - mn1);
                m0v = mn0; m1v = mn1;
                float ps0 = 0.f, ps1 = 0.f;
                #pragma unroll
                for (int s = 0; s < 4; s++) {
                    #pragma unroll
                    for (int half = 0; half < 2; half++) {
                        int t = 2 * s + half;
                        __half2 e0 = h2exp2(__floats2half2_rn(c[t][0] - mn0, c[t][1] - mn0));
                        __half2 e1 = h2exp2(__floats2half2_rn(c[t][2] - mn1, c[t][3] - mn1));
                        ap[s][half * 2 + 0] = *(uint32_t*)&e0;
                        ap[s][half * 2 + 1] = *(uint32_t*)&e1;
                        float2 fa = __half22float2(e0);
                        float2 fb = __half22float2(e1);
                        ps0 += fa.x + fa.y;
                        ps1 += fb.x + fb.y;
                    }
                }
                ps0 += __shfl_xor_sync(0xffffffffu, ps0, 1);
                ps0 += __shfl_xor_sync(0xffffffffu, ps0, 2);
                ps1 += __shfl_xor_sync(0xffffffffu, ps1, 1);
                ps1 += __shfl_xor_sync(0xffffffffu, ps1, 2);
                l0 = l0 * f0 + ps0;
                l1 = l1 * f1 + ps1;
                #pragma unroll
                for (int t = 0; t < 8; t++) {
                    o[t][0] *= f0; o[t][1] *= f0;
                    o[t][2] *= f1; o[t][3] *= f1;
                }
            }

            // ---- O += P V ----
            #pragma unroll
            for (int s = 0; s < 4; s++) {
                int chunk = s * 2 + (lane >> 4);
                uint32_t bf[8][2];
                #pragma unroll
                for (int p = 0; p < 4; p++) {
                    int rd = p * 16 + (lane & 15);
                    uint32_t off = (uint32_t)(rd * 128 + ((chunk ^ (rd & 7)) * 16));
                    uint32_t t0, t1, t2, t3;
                    ldsm_x4(sV + off, t0, t1, t2, t3);
                    bf[2*p][0] = t0; bf[2*p][1] = t2; bf[2*p+1][0] = t1; bf[2*p+1][1] = t3;
                }
                #pragma unroll
                for (int nt = 0; nt < 8; nt++) mma_f16(o[nt], ap[s], bf[nt]);
            }
        }

        __syncthreads();
        if (it + 2 < 8) load_stage(it + 2, it & 1);
        CP_COMMIT();
    }

    float inv0 = 1.0f / l0, inv1 = 1.0f / l1;
    int r = lane >> 2;
    int row0 = q0 + wq * 16 + r;
    size_t base0 = ((size_t)(b * N_) + row0) * E_ + h * 64 + (lane & 3) * 2;
    size_t base1 = base0 + (size_t)8 * E_;
    #pragma unroll
    for (int t = 0; t < 8; t++) {
        *(uint32_t*)(Oo + base0 + t * 8) = packh2(o[t][0] * inv0, o[t][1] * inv0);
        *(uint32_t*)(Oo + base1 + t * 8) = packh2(o[t][2] * inv1, o[t][3] * inv1);
    }
}

// ---------------------------------------------------------------------------
extern "C" void kernel_launch(void* const* d_in, const int* in_sizes, int n_in,
                              void* d_out, int out_size)
{
    (void)in_sizes; (void)n_in; (void)out_size;
    const float* x      = (const float*)d_in[0];
    const float* w_qkv  = (const float*)d_in[1];
    const float* b_qkv  = (const float*)d_in[2];
    const float* w_proj = (const float*)d_in[3];
    const float* b_proj = (const float*)d_in[4];
    float* out = (float*)d_out;

    __half *xf, *wq, *wp, *ao, *q2, *k2, *vt;
    float2* rope;
    cudaGetSymbolAddress((void**)&xf, g_x);
    cudaGetSymbolAddress((void**)&wq, g_wq);
    cudaGetSymbolAddress((void**)&wp, g_wp);
    cudaGetSymbolAddress((void**)&ao, g_ao);
    cudaGetSymbolAddress((void**)&q2, g_q2);
    cudaGetSymbolAddress((void**)&k2, g_k2);
    cudaGetSymbolAddress((void**)&vt, g_vt);
    cudaGetSymbolAddress((void**)&rope, g_rope);

    const int GEMM_SMEM = 66560;
    cudaFuncSetAttribute(tc_gemm_qkv, cudaFuncAttributeMaxDynamicSharedMemorySize, GEMM_SMEM);
    cudaFuncSetAttribute(tc_gemm, cudaFuncAttributeMaxDynamicSharedMemorySize, GEMM_SMEM);
    const int ATTN_SMEM = 16384 + 2 * 32768;
    cudaFuncSetAttribute(attn_mma, cudaFuncAttributeMaxDynamicSharedMemorySize, ATTN_SMEM);

    // fused prep: x convert + both weight transposes + rope table
    prep_all<<<XBLOCKS + WQTILES + WPTILES + 2, 256>>>(
        (const float4*)x, (uint2*)xf, w_qkv, wq, w_proj, wp, rope);
    {
        dim3 grid(3 * E_ / 128, M_ / 128);
        tc_gemm_qkv<<<grid, 128, GEMM_SMEM>>>(xf, wq, b_qkv, rope, q2, k2, vt);
    }
    {
        dim3 grid(N_ / 128, B_ * H_);
        attn_mma<<<grid, 256, ATTN_SMEM>>>(q2, k2, vt, ao);
    }
    {
        dim3 grid(E_ / 128, M_ / 128);
        tc_gemm<<<grid, 128, GEMM_SMEM>>>(ao, wp, b_proj, out, E_, E_);
    }
}